// round 6
// baseline (speedup 1.0000x reference)
#include <cuda_runtime.h>
#include <cuda_fp16.h>
#include <cstdint>

// Problem constants
#define Bc   1024
#define Tc   512
#define EMBc 100
#define H1c  128
#define G1c  512   // 4*H1
#define H2c  64
#define G2c  256   // 4*H2
#define Mtot (Bc*Tc)  // 524288

// Scratch (fp16): 512MiB + 128MiB + 256MiB
__device__ __half g_xw1[(size_t)Mtot * G1c];
__device__ __half g_hs1[(size_t)Mtot * H1c];
__device__ __half g_xw2[(size_t)Mtot * G2c];

// ---------------------------------------------------------------------------
// helpers
// ---------------------------------------------------------------------------
__device__ __forceinline__ uint32_t s2u(const void* p) {
    return (uint32_t)__cvta_generic_to_shared(p);
}
__device__ __forceinline__ void ldm_x4(uint32_t& a0, uint32_t& a1, uint32_t& a2, uint32_t& a3,
                                       uint32_t addr) {
    asm volatile("ldmatrix.sync.aligned.m8n8.x4.shared.b16 {%0,%1,%2,%3}, [%4];"
                 : "=r"(a0), "=r"(a1), "=r"(a2), "=r"(a3) : "r"(addr));
}
__device__ __forceinline__ void ldm_x2(uint32_t& b0, uint32_t& b1, uint32_t addr) {
    asm volatile("ldmatrix.sync.aligned.m8n8.x2.shared.b16 {%0,%1}, [%2];"
                 : "=r"(b0), "=r"(b1) : "r"(addr));
}
__device__ __forceinline__ void mma16816(float* d, const uint32_t* a, const uint32_t* b) {
    asm volatile("mma.sync.aligned.m16n8k16.row.col.f32.f16.f16.f32 "
                 "{%0,%1,%2,%3}, {%4,%5,%6,%7}, {%8,%9}, {%0,%1,%2,%3};"
                 : "+f"(d[0]), "+f"(d[1]), "+f"(d[2]), "+f"(d[3])
                 : "r"(a[0]), "r"(a[1]), "r"(a[2]), "r"(a[3]), "r"(b[0]), "r"(b[1]));
}
__device__ __forceinline__ float tanhfast(float x) {
    float y;
    asm("tanh.approx.f32 %0, %1;" : "=f"(y) : "f"(x));
    return y;
}
__device__ __forceinline__ float sigfast(float x) {
    return 0.5f * tanhfast(0.5f * x) + 0.5f;
}
__device__ __forceinline__ __half2 u2h2(uint32_t v) {
    __half2 h;
    *reinterpret_cast<uint32_t*>(&h) = v;
    return h;
}

// ---------------------------------------------------------------------------
// fp16 tensor-core GEMM: out[m][n] = half(sum_k A[m][k]*W[n][k] + ba[n] + bb[n])
// BM=128, BN=128, BK=32, 256 threads, warp grid 2(m) x 4(n), m16n8k16 HMMA.
// A: fp32 (AHALF=false) or fp16 (AHALF=true). W fp32. Output fp16.
// ---------------------------------------------------------------------------
template <int N, int K, bool AHALF>
__global__ void __launch_bounds__(256) gemm_hmma(const void* __restrict__ A_,
                                                 const float* __restrict__ W,
                                                 const float* __restrict__ ba,
                                                 const float* __restrict__ bb,
                                                 __half* __restrict__ out)
{
    constexpr int BM = 128, BN = 128, BK = 32;
    constexpr int LDS_ = 40;                 // padded half stride (80B)
    constexpr int KT = (K + BK - 1) / BK;

    __shared__ alignas(16) __half As[BM * LDS_];
    __shared__ alignas(16) __half Ws[BN * LDS_];

    const int tid  = threadIdx.x;
    const int bm   = blockIdx.y * BM;
    const int bn   = blockIdx.x * BN;
    const int w    = tid >> 5;
    const int lane = tid & 31;
    const int wm   = (w >> 2) * 64;
    const int wn   = (w & 3) * 32;

    float acc[4][4][4];
#pragma unroll
    for (int mt = 0; mt < 4; mt++)
#pragma unroll
        for (int nt = 0; nt < 4; nt++)
#pragma unroll
            for (int i = 0; i < 4; i++) acc[mt][nt][i] = 0.f;

    for (int kt = 0; kt < KT; kt++) {
        const int kbase = kt * BK;
        if constexpr (AHALF) {
            const __half* A = (const __half*)A_;
            // 128 rows x 4 uint4 chunks (8 halves each) per 32-k tile
#pragma unroll
            for (int i = 0; i < 2; i++) {
                int idx = tid + i * 256;           // 0..511
                int m = idx >> 2, c = idx & 3;
                uint4 v = *(const uint4*)(A + (size_t)(bm + m) * K + kbase + c * 8);
                *(uint4*)&As[m * LDS_ + c * 8] = v;
            }
        } else {
            const float* A = (const float*)A_;
#pragma unroll
            for (int i = 0; i < 8; i++) {
                int idx = tid + i * 256;           // 0..2047
                int m = idx >> 4, kc = idx & 15;
                int k = kbase + kc * 2;
                float2 v = make_float2(0.f, 0.f);
                if (k + 1 < K)      v = *(const float2*)(A + (size_t)(bm + m) * K + k);
                else if (k < K)     v.x = A[(size_t)(bm + m) * K + k];
                *(__half2*)&As[m * LDS_ + kc * 2] = __floats2half2_rn(v.x, v.y);
            }
        }
#pragma unroll
        for (int i = 0; i < 8; i++) {
            int idx = tid + i * 256;
            int n = idx >> 4, kc = idx & 15;
            int k = kbase + kc * 2;
            float2 v = make_float2(0.f, 0.f);
            if (k + 1 < K)      v = *(const float2*)(W + (size_t)(bn + n) * K + k);
            else if (k < K)     v.x = W[(size_t)(bn + n) * K + k];
            *(__half2*)&Ws[n * LDS_ + kc * 2] = __floats2half2_rn(v.x, v.y);
        }
        __syncthreads();

#pragma unroll
        for (int kk = 0; kk < BK; kk += 16) {
            uint32_t af[4][4];
#pragma unroll
            for (int mt = 0; mt < 4; mt++) {
                uint32_t addr = s2u(&As[(wm + mt * 16 + (lane & 15)) * LDS_ + kk + (lane >> 4) * 8]);
                ldm_x4(af[mt][0], af[mt][1], af[mt][2], af[mt][3], addr);
            }
            uint32_t bf[4][2];
#pragma unroll
            for (int nt = 0; nt < 4; nt++) {
                int l = lane & 15;
                uint32_t addr = s2u(&Ws[(wn + nt * 8 + (l & 7)) * LDS_ + kk + ((l >> 3) & 1) * 8]);
                ldm_x2(bf[nt][0], bf[nt][1], addr);
            }
#pragma unroll
            for (int mt = 0; mt < 4; mt++)
#pragma unroll
                for (int nt = 0; nt < 4; nt++)
                    mma16816(acc[mt][nt], af[mt], bf[nt]);
        }
        __syncthreads();
    }

#pragma unroll
    for (int mt = 0; mt < 4; mt++) {
#pragma unroll
        for (int nt = 0; nt < 4; nt++) {
            int row = bm + wm + mt * 16 + (lane >> 2);
            int col = bn + wn + nt * 8 + (lane & 3) * 2;
            float b0 = __ldg(ba + col) + __ldg(bb + col);
            float b1 = __ldg(ba + col + 1) + __ldg(bb + col + 1);
            *(__half2*)(out + (size_t)row * N + col) =
                __floats2half2_rn(acc[mt][nt][0] + b0, acc[mt][nt][1] + b1);
            *(__half2*)(out + (size_t)(row + 8) * N + col) =
                __floats2half2_rn(acc[mt][nt][2] + b0, acc[mt][nt][3] + b1);
        }
    }
}

// ---------------------------------------------------------------------------
// LSTM layer 1: 128 blocks x 1024 threads (32 warps/SM), 8 batch rows/block.
// Phase 1: thread (g=tid&511, kh=tid>>9) computes half the 128-dot for gate
//          row g over 8 batch rows; 32 half2 weight REGISTERS per thread.
// Phase 2: thread (row=tid>>7, j=tid&127): one hidden unit per thread.
// ---------------------------------------------------------------------------
__global__ void __launch_bounds__(1024) lstm1_kernel(const __half* __restrict__ xw,   // [B][T][512] fp16
                                                     const float* __restrict__ Whh,   // [512][128]
                                                     __half* __restrict__ hs1)        // [B][T][128] fp16
{
    __shared__ float   gpart[2][8][512];    // 32KB
    __shared__ __half2 hsh[8][64];          // 2KB

    const int tid = threadIdx.x;
    const int b0  = blockIdx.x * 8;
    const int g   = tid & 511;
    const int kh  = tid >> 9;               // 0/1: k-half

    // weights -> registers (time-invariant): rows g, k in [kh*64, kh*64+64)
    __half2 wr[32];
    {
        const float* wp = Whh + (size_t)g * 128 + kh * 64;
#pragma unroll
        for (int i = 0; i < 32; i++) wr[i] = __floats2half2_rn(wp[2 * i], wp[2 * i + 1]);
    }

    const int arow = tid >> 7;   // 0..7
    const int aj   = tid & 127;  // hidden unit

    if (tid < 512) ((__half2*)hsh)[tid] = __floats2half2_rn(0.f, 0.f);
    __syncthreads();

    const __half* xbase = xw + (size_t)(b0 + arow) * Tc * 512;
    __half px[4];
#pragma unroll
    for (int gg = 0; gg < 4; gg++) px[gg] = xbase[gg * 128 + aj];

    float c = 0.f;

    for (int t = 0; t < Tc; t++) {
        // ---- phase 1 ----
        __half2 acc[8];
#pragma unroll
        for (int r = 0; r < 8; r++) acc[r] = __floats2half2_rn(0.f, 0.f);

#pragma unroll
        for (int kp = 0; kp < 32; kp += 4) {
            __half2 w0 = wr[kp], w1 = wr[kp + 1], w2 = wr[kp + 2], w3 = wr[kp + 3];
#pragma unroll
            for (int r = 0; r < 8; r++) {
                uint4 hv = *(const uint4*)&hsh[r][kh * 32 + kp];   // broadcast LDS.128
                acc[r] = __hfma2(w0, u2h2(hv.x), acc[r]);
                acc[r] = __hfma2(w1, u2h2(hv.y), acc[r]);
                acc[r] = __hfma2(w2, u2h2(hv.z), acc[r]);
                acc[r] = __hfma2(w3, u2h2(hv.w), acc[r]);
            }
        }
#pragma unroll
        for (int r = 0; r < 8; r++) {
            float2 p = __half22float2(acc[r]);
            gpart[kh][r][g] = p.x + p.y;
        }
        __syncthreads();

        // ---- phase 2: one unit per thread ----
        {
            float zi = gpart[0][arow][aj]       + gpart[1][arow][aj]       + __half2float(px[0]);
            float zf = gpart[0][arow][128 + aj] + gpart[1][arow][128 + aj] + __half2float(px[1]);
            float zg = gpart[0][arow][256 + aj] + gpart[1][arow][256 + aj] + __half2float(px[2]);
            float zo = gpart[0][arow][384 + aj] + gpart[1][arow][384 + aj] + __half2float(px[3]);

            c = sigfast(zf) * c + sigfast(zi) * tanhfast(zg);
            float h = sigfast(zo) * tanhfast(c);

            __half hh = __float2half_rn(h);
            ((__half*)&hsh[arow][0])[aj] = hh;
            hs1[((size_t)(b0 + arow) * Tc + t) * 128 + aj] = hh;

            if (t + 1 < Tc) {
                const __half* xr = xbase + (size_t)(t + 1) * 512;
#pragma unroll
                for (int gg = 0; gg < 4; gg++) px[gg] = xr[gg * 128 + aj];
            }
        }
        __syncthreads();
    }
}

// ---------------------------------------------------------------------------
// LSTM layer 2 + FC head: 128 blocks x 1024 threads, 8 rows/block.
// Phase 1: thread (g=tid&255, kq=tid>>8) computes quarter-dot for gate row g
//          over 8 rows; 8 half2 weight regs.
// Phase 2: threads 0..511: (row=tid>>6, j=tid&63), one unit each.
// ---------------------------------------------------------------------------
__global__ void __launch_bounds__(1024) lstm2_kernel(const __half* __restrict__ xw,   // [B][T][256] fp16
                                                     const float* __restrict__ Whh,   // [256][64]
                                                     const float* __restrict__ fc1w,
                                                     const float* __restrict__ fc1b,
                                                     const float* __restrict__ fc2w,
                                                     const float* __restrict__ fc2b,
                                                     float* __restrict__ out)
{
    __shared__ float   gpart[4][8][256];    // 32KB
    __shared__ __half2 hsh[8][32];          // 1KB
    __shared__ float   hfin[8][64];         // 2KB

    const int tid = threadIdx.x;
    const int b0  = blockIdx.x * 8;
    const int g   = tid & 255;
    const int kq  = tid >> 8;               // 0..3: k-quarter

    __half2 wr[8];
    {
        const float* wp = Whh + (size_t)g * 64 + kq * 16;
#pragma unroll
        for (int i = 0; i < 8; i++) wr[i] = __floats2half2_rn(wp[2 * i], wp[2 * i + 1]);
    }

    const int arow = tid >> 6;   // 0..7 (valid tid<512)
    const int aj   = tid & 63;

    if (tid < 256) ((__half2*)hsh)[tid] = __floats2half2_rn(0.f, 0.f);
    __syncthreads();

    const __half* xbase = xw + (size_t)(b0 + arow) * Tc * 256;
    __half px[4];
    if (tid < 512) {
#pragma unroll
        for (int gg = 0; gg < 4; gg++) px[gg] = xbase[gg * 64 + aj];
    }

    float c = 0.f;

    for (int t = 0; t < Tc; t++) {
        __half2 acc[8];
#pragma unroll
        for (int r = 0; r < 8; r++) acc[r] = __floats2half2_rn(0.f, 0.f);

#pragma unroll
        for (int kp = 0; kp < 8; kp += 4) {
            __half2 w0 = wr[kp], w1 = wr[kp + 1], w2 = wr[kp + 2], w3 = wr[kp + 3];
#pragma unroll
            for (int r = 0; r < 8; r++) {
                uint4 hv = *(const uint4*)&hsh[r][kq * 8 + kp];
                acc[r] = __hfma2(w0, u2h2(hv.x), acc[r]);
                acc[r] = __hfma2(w1, u2h2(hv.y), acc[r]);
                acc[r] = __hfma2(w2, u2h2(hv.z), acc[r]);
                acc[r] = __hfma2(w3, u2h2(hv.w), acc[r]);
            }
        }
#pragma unroll
        for (int r = 0; r < 8; r++) {
            float2 p = __half22float2(acc[r]);
            gpart[kq][r][g] = p.x + p.y;
        }
        __syncthreads();

        if (tid < 512) {
            float zi = __half2float(px[0]);
            float zf = __half2float(px[1]);
            float zg = __half2float(px[2]);
            float zo = __half2float(px[3]);
#pragma unroll
            for (int q = 0; q < 4; q++) {
                zi += gpart[q][arow][aj];
                zf += gpart[q][arow][64 + aj];
                zg += gpart[q][arow][128 + aj];
                zo += gpart[q][arow][192 + aj];
            }

            c = sigfast(zf) * c + sigfast(zi) * tanhfast(zg);
            float h = sigfast(zo) * tanhfast(c);

            ((__half*)&hsh[arow][0])[aj] = __float2half_rn(h);
            if (t == Tc - 1) hfin[arow][aj] = h;

            if (t + 1 < Tc) {
                const __half* xr = xbase + (size_t)(t + 1) * 256;
#pragma unroll
                for (int gg = 0; gg < 4; gg++) px[gg] = xr[gg * 64 + aj];
            }
        }
        __syncthreads();
    }

    // FC head: warp w -> batch row w (warps 0..7), lane = fc1 unit
    const int warp = tid >> 5, lane = tid & 31;
    if (warp < 8) {
        float a = __ldg(fc1b + lane);
#pragma unroll
        for (int k = 0; k < 64; k++)
            a = fmaf(hfin[warp][k], __ldg(fc1w + lane * 64 + k), a);
        a = fmaxf(a, 0.f);
        float v = a * __ldg(fc2w + lane);
#pragma unroll
        for (int off = 16; off; off >>= 1) v += __shfl_down_sync(0xffffffffu, v, off);
        if (lane == 0) out[b0 + warp] = 1.f / (1.f + __expf(-(v + __ldg(fc2b))));
    }
}

// ---------------------------------------------------------------------------
extern "C" void kernel_launch(void* const* d_in, const int* in_sizes, int n_in,
                              void* d_out, int out_size)
{
    (void)in_sizes; (void)n_in; (void)out_size;
    const float* X     = (const float*)d_in[0];
    const float* W1_ih = (const float*)d_in[1];
    const float* W1_hh = (const float*)d_in[2];
    const float* b1_ih = (const float*)d_in[3];
    const float* b1_hh = (const float*)d_in[4];
    const float* W2_ih = (const float*)d_in[5];
    const float* W2_hh = (const float*)d_in[6];
    const float* b2_ih = (const float*)d_in[7];
    const float* b2_hh = (const float*)d_in[8];
    const float* fc1w  = (const float*)d_in[9];
    const float* fc1b  = (const float*)d_in[10];
    const float* fc2w  = (const float*)d_in[11];
    const float* fc2b  = (const float*)d_in[12];
    float* out = (float*)d_out;

    __half *xw1, *hs1, *xw2;
    cudaGetSymbolAddress((void**)&xw1, g_xw1);
    cudaGetSymbolAddress((void**)&hs1, g_hs1);
    cudaGetSymbolAddress((void**)&xw2, g_xw2);

    // 1) xw1 = half(X @ W1_ih^T + b)
    gemm_hmma<G1c, EMBc, false><<<dim3(G1c / 128, Mtot / 128), 256>>>(X, W1_ih, b1_ih, b1_hh, xw1);
    // 2) layer-1 recurrence
    lstm1_kernel<<<Bc / 8, 1024>>>(xw1, W1_hh, hs1);
    // 3) xw2 = half(hs1 @ W2_ih^T + b)
    gemm_hmma<G2c, H1c, true><<<dim3(G2c / 128, Mtot / 128), 256>>>(hs1, W2_ih, b2_ih, b2_hh, xw2);
    // 4) layer-2 recurrence + FC head
    lstm2_kernel<<<Bc / 8, 1024>>>(xw2, W2_hh, fc1w, fc1b, fc2w, fc2b, out);
}

// round 7
// speedup vs baseline: 1.6824x; 1.6824x over previous
#include <cuda_runtime.h>
#include <cuda_fp16.h>
#include <cstdint>

// Problem constants
#define Bc   1024
#define Tc   512
#define EMBc 100
#define H1c  128
#define G1c  512   // 4*H1
#define H2c  64
#define G2c  256   // 4*H2
#define Mtot (Bc*Tc)  // 524288

// Scratch (fp16)
__device__ __half g_xw1[(size_t)Mtot * G1c];
__device__ __half g_hs1[(size_t)Mtot * H1c];
__device__ __half g_xw2[(size_t)Mtot * G2c];

// ---------------------------------------------------------------------------
// helpers
// ---------------------------------------------------------------------------
__device__ __forceinline__ uint32_t s2u(const void* p) {
    return (uint32_t)__cvta_generic_to_shared(p);
}
__device__ __forceinline__ void ldm_x4(uint32_t& a0, uint32_t& a1, uint32_t& a2, uint32_t& a3,
                                       uint32_t addr) {
    asm volatile("ldmatrix.sync.aligned.m8n8.x4.shared.b16 {%0,%1,%2,%3}, [%4];"
                 : "=r"(a0), "=r"(a1), "=r"(a2), "=r"(a3) : "r"(addr));
}
__device__ __forceinline__ void ldm_x2(uint32_t& b0, uint32_t& b1, uint32_t addr) {
    asm volatile("ldmatrix.sync.aligned.m8n8.x2.shared.b16 {%0,%1}, [%2];"
                 : "=r"(b0), "=r"(b1) : "r"(addr));
}
__device__ __forceinline__ void mma16816(float* d, const uint32_t* a, const uint32_t* b) {
    asm volatile("mma.sync.aligned.m16n8k16.row.col.f32.f16.f16.f32 "
                 "{%0,%1,%2,%3}, {%4,%5,%6,%7}, {%8,%9}, {%0,%1,%2,%3};"
                 : "+f"(d[0]), "+f"(d[1]), "+f"(d[2]), "+f"(d[3])
                 : "r"(a[0]), "r"(a[1]), "r"(a[2]), "r"(a[3]), "r"(b[0]), "r"(b[1]));
}
__device__ __forceinline__ float tanhfast(float x) {
    float y;
    asm("tanh.approx.f32 %0, %1;" : "=f"(y) : "f"(x));
    return y;
}
__device__ __forceinline__ float sigfast(float x) {
    return 0.5f * tanhfast(0.5f * x) + 0.5f;
}
// pack two fp32 -> half2 (as uint32 for mma frags)
__device__ __forceinline__ uint32_t packh2(float x, float y) {
    __half2 h = __floats2half2_rn(x, y);
    return *reinterpret_cast<uint32_t*>(&h);
}

// ---------------------------------------------------------------------------
// fp16 tensor-core GEMM (unchanged, known-good):
// out[m][n] = half(sum_k A[m][k]*W[n][k] + ba[n] + bb[n])
// ---------------------------------------------------------------------------
template <int N, int K, bool AHALF>
__global__ void __launch_bounds__(256) gemm_hmma(const void* __restrict__ A_,
                                                 const float* __restrict__ W,
                                                 const float* __restrict__ ba,
                                                 const float* __restrict__ bb,
                                                 __half* __restrict__ out)
{
    constexpr int BM = 128, BN = 128, BK = 32;
    constexpr int LDS_ = 40;
    constexpr int KT = (K + BK - 1) / BK;

    __shared__ alignas(16) __half As[BM * LDS_];
    __shared__ alignas(16) __half Ws[BN * LDS_];

    const int tid  = threadIdx.x;
    const int bm   = blockIdx.y * BM;
    const int bn   = blockIdx.x * BN;
    const int w    = tid >> 5;
    const int lane = tid & 31;
    const int wm   = (w >> 2) * 64;
    const int wn   = (w & 3) * 32;

    float acc[4][4][4];
#pragma unroll
    for (int mt = 0; mt < 4; mt++)
#pragma unroll
        for (int nt = 0; nt < 4; nt++)
#pragma unroll
            for (int i = 0; i < 4; i++) acc[mt][nt][i] = 0.f;

    for (int kt = 0; kt < KT; kt++) {
        const int kbase = kt * BK;
        if constexpr (AHALF) {
            const __half* A = (const __half*)A_;
#pragma unroll
            for (int i = 0; i < 2; i++) {
                int idx = tid + i * 256;
                int m = idx >> 2, c = idx & 3;
                uint4 v = *(const uint4*)(A + (size_t)(bm + m) * K + kbase + c * 8);
                *(uint4*)&As[m * LDS_ + c * 8] = v;
            }
        } else {
            const float* A = (const float*)A_;
#pragma unroll
            for (int i = 0; i < 8; i++) {
                int idx = tid + i * 256;
                int m = idx >> 4, kc = idx & 15;
                int k = kbase + kc * 2;
                float2 v = make_float2(0.f, 0.f);
                if (k + 1 < K)      v = *(const float2*)(A + (size_t)(bm + m) * K + k);
                else if (k < K)     v.x = A[(size_t)(bm + m) * K + k];
                *(__half2*)&As[m * LDS_ + kc * 2] = __floats2half2_rn(v.x, v.y);
            }
        }
#pragma unroll
        for (int i = 0; i < 8; i++) {
            int idx = tid + i * 256;
            int n = idx >> 4, kc = idx & 15;
            int k = kbase + kc * 2;
            float2 v = make_float2(0.f, 0.f);
            if (k + 1 < K)      v = *(const float2*)(W + (size_t)(bn + n) * K + k);
            else if (k < K)     v.x = W[(size_t)(bn + n) * K + k];
            *(__half2*)&Ws[n * LDS_ + kc * 2] = __floats2half2_rn(v.x, v.y);
        }
        __syncthreads();

#pragma unroll
        for (int kk = 0; kk < BK; kk += 16) {
            uint32_t af[4][4];
#pragma unroll
            for (int mt = 0; mt < 4; mt++) {
                uint32_t addr = s2u(&As[(wm + mt * 16 + (lane & 15)) * LDS_ + kk + (lane >> 4) * 8]);
                ldm_x4(af[mt][0], af[mt][1], af[mt][2], af[mt][3], addr);
            }
            uint32_t bf[4][2];
#pragma unroll
            for (int nt = 0; nt < 4; nt++) {
                int l = lane & 15;
                uint32_t addr = s2u(&Ws[(wn + nt * 8 + (l & 7)) * LDS_ + kk + ((l >> 3) & 1) * 8]);
                ldm_x2(bf[nt][0], bf[nt][1], addr);
            }
#pragma unroll
            for (int mt = 0; mt < 4; mt++)
#pragma unroll
                for (int nt = 0; nt < 4; nt++)
                    mma16816(acc[mt][nt], af[mt], bf[nt]);
        }
        __syncthreads();
    }

#pragma unroll
    for (int mt = 0; mt < 4; mt++) {
#pragma unroll
        for (int nt = 0; nt < 4; nt++) {
            int row = bm + wm + mt * 16 + (lane >> 2);
            int col = bn + wn + nt * 8 + (lane & 3) * 2;
            float b0 = __ldg(ba + col) + __ldg(bb + col);
            float b1 = __ldg(ba + col + 1) + __ldg(bb + col + 1);
            *(__half2*)(out + (size_t)row * N + col) =
                __floats2half2_rn(acc[mt][nt][0] + b0, acc[mt][nt][1] + b1);
            *(__half2*)(out + (size_t)(row + 8) * N + col) =
                __floats2half2_rn(acc[mt][nt][2] + b0, acc[mt][nt][3] + b1);
        }
    }
}

// ---------------------------------------------------------------------------
// LSTM layer 1 (tensor-core recurrence).
// 128 blocks x 512 threads (16 warps), 8 batch rows/block.
// Phase 1: D[gate, row] = W_hh @ h via m16n8k16. Warp w owns gates
//          [w*32, w*32+32) = 2 m16 tiles; A fragments (W_hh fp16) persist in
//          registers across all 512 steps (loaded directly from gmem with the
//          PTX fragment layout). B = h, ldmatrix'd from hsh[8][136] each step.
// Phase 2: thread (row=tid>>6, units 2*(tid&63), +1) does activations.
// ---------------------------------------------------------------------------
__global__ void __launch_bounds__(512) lstm1_kernel(const __half* __restrict__ xw,   // [B][T][512]
                                                    const float* __restrict__ Whh,   // [512][128]
                                                    __half* __restrict__ hs1)        // [B][T][128]
{
    constexpr int HP = 136;                   // padded h row (halves)
    __shared__ float  gsum[512 * 10];         // [gate][row(8) pad 10]  20KB
    __shared__ __half hsh[8 * HP];            // [row][k]               2.1KB

    const int tid  = threadIdx.x;
    const int w    = tid >> 5;
    const int lane = tid & 31;
    const int b0   = blockIdx.x * 8;

    // ---- A fragments: W_hh rows [w*32, w*32+32), fp16, persistent ----
    // frag layout per (mt, ks): a0=(r,k) a1=(r+8,k) a2=(r,k+8) a3=(r+8,k+8)
    // with r = g0 + lane/4, k = ks*16 + (lane%4)*2
    uint32_t afr[2][8][4];
    {
        const int gr = w * 32 + (lane >> 2);
        const int kc = (lane & 3) * 2;
#pragma unroll
        for (int mt = 0; mt < 2; mt++) {
            const float* r0 = Whh + (size_t)(gr + mt * 16) * 128;
            const float* r8 = r0 + 8 * 128;
#pragma unroll
            for (int ks = 0; ks < 8; ks++) {
                int k = ks * 16 + kc;
                afr[mt][ks][0] = packh2(r0[k],     r0[k + 1]);
                afr[mt][ks][1] = packh2(r8[k],     r8[k + 1]);
                afr[mt][ks][2] = packh2(r0[k + 8], r0[k + 9]);
                afr[mt][ks][3] = packh2(r8[k + 8], r8[k + 9]);
            }
        }
    }

    // zero h state
    for (int i = tid; i < 8 * HP / 2; i += 512) ((__half2*)hsh)[i] = __floats2half2_rn(0.f, 0.f);
    __syncthreads();

    // phase-2 identity
    const int arow = tid >> 6;          // 0..7
    const int aj2  = (tid & 63) * 2;    // units aj2, aj2+1

    const __half* xbase = xw + (size_t)(b0 + arow) * Tc * 512;
    __half2 px[4];
#pragma unroll
    for (int gg = 0; gg < 4; gg++)
        px[gg] = *(const __half2*)(xbase + gg * 128 + aj2);

    float c0 = 0.f, c1 = 0.f;

    for (int t = 0; t < Tc; t++) {
        // ---- phase 1: MMA ----
        {
            uint32_t bf[8][2];
            const int l = lane & 15;
            uint32_t baddr = s2u(&hsh[(l & 7) * HP + ((l >> 3) & 1) * 8]);
#pragma unroll
            for (int ks = 0; ks < 8; ks++)
                ldm_x2(bf[ks][0], bf[ks][1], baddr + ks * 32);   // +16 halves

            float acc[2][4];
#pragma unroll
            for (int mt = 0; mt < 2; mt++) {
#pragma unroll
                for (int i = 0; i < 4; i++) acc[mt][i] = 0.f;
#pragma unroll
                for (int ks = 0; ks < 8; ks++)
                    mma16816(acc[mt], afr[mt][ks], bf[ks]);
            }
            const int gr = w * 32 + (lane >> 2);
            const int n0 = (lane & 3) * 2;
#pragma unroll
            for (int mt = 0; mt < 2; mt++) {
                *(float2*)&gsum[(gr + mt * 16) * 10 + n0]     = make_float2(acc[mt][0], acc[mt][1]);
                *(float2*)&gsum[(gr + mt * 16 + 8) * 10 + n0] = make_float2(acc[mt][2], acc[mt][3]);
            }
        }
        __syncthreads();

        // ---- phase 2: activations, 2 units/thread ----
        {
            float2 p0 = __half22float2(px[0]);
            float2 p1 = __half22float2(px[1]);
            float2 p2 = __half22float2(px[2]);
            float2 p3 = __half22float2(px[3]);
            float zi0 = gsum[(aj2)*10 + arow]           + p0.x;
            float zi1 = gsum[(aj2 + 1)*10 + arow]       + p0.y;
            float zf0 = gsum[(128 + aj2)*10 + arow]     + p1.x;
            float zf1 = gsum[(128 + aj2 + 1)*10 + arow] + p1.y;
            float zg0 = gsum[(256 + aj2)*10 + arow]     + p2.x;
            float zg1 = gsum[(256 + aj2 + 1)*10 + arow] + p2.y;
            float zo0 = gsum[(384 + aj2)*10 + arow]     + p3.x;
            float zo1 = gsum[(384 + aj2 + 1)*10 + arow] + p3.y;

            c0 = sigfast(zf0) * c0 + sigfast(zi0) * tanhfast(zg0);
            float h0 = sigfast(zo0) * tanhfast(c0);
            c1 = sigfast(zf1) * c1 + sigfast(zi1) * tanhfast(zg1);
            float h1 = sigfast(zo1) * tanhfast(c1);

            __half2 hh = __floats2half2_rn(h0, h1);
            *(__half2*)&hsh[arow * HP + aj2] = hh;
            *(__half2*)(hs1 + ((size_t)(b0 + arow) * Tc + t) * 128 + aj2) = hh;

            if (t + 1 < Tc) {
                const __half* xr = xbase + (size_t)(t + 1) * 512;
#pragma unroll
                for (int gg = 0; gg < 4; gg++)
                    px[gg] = *(const __half2*)(xr + gg * 128 + aj2);
            }
        }
        __syncthreads();
    }
}

// ---------------------------------------------------------------------------
// LSTM layer 2 (tensor-core recurrence) + fused FC head.
// 128 blocks x 512 threads (16 warps), 8 rows/block. Warp w owns gates
// [w*16, w*16+16) = 1 m16 tile, k=64 -> 4 k-steps, A frags persistent.
// Phase 2: thread (row=tid>>6, unit=tid&63), 1 unit each.
// ---------------------------------------------------------------------------
__global__ void __launch_bounds__(512) lstm2_kernel(const __half* __restrict__ xw,   // [B][T][256]
                                                    const float* __restrict__ Whh,   // [256][64]
                                                    const float* __restrict__ fc1w,
                                                    const float* __restrict__ fc1b,
                                                    const float* __restrict__ fc2w,
                                                    const float* __restrict__ fc2b,
                                                    float* __restrict__ out)
{
    constexpr int HP = 72;                    // padded h row (halves)
    __shared__ float  gsum[256 * 10];         // 10KB
    __shared__ __half hsh[8 * HP];            // 1.1KB
    __shared__ float  hfin[8][64];            // 2KB

    const int tid  = threadIdx.x;
    const int w    = tid >> 5;
    const int lane = tid & 31;
    const int b0   = blockIdx.x * 8;

    uint32_t afr[4][4];
    {
        const int gr = w * 16 + (lane >> 2);
        const int kc = (lane & 3) * 2;
        const float* r0 = Whh + (size_t)gr * 64;
        const float* r8 = r0 + 8 * 64;
#pragma unroll
        for (int ks = 0; ks < 4; ks++) {
            int k = ks * 16 + kc;
            afr[ks][0] = packh2(r0[k],     r0[k + 1]);
            afr[ks][1] = packh2(r8[k],     r8[k + 1]);
            afr[ks][2] = packh2(r0[k + 8], r0[k + 9]);
            afr[ks][3] = packh2(r8[k + 8], r8[k + 9]);
        }
    }

    for (int i = tid; i < 8 * HP / 2; i += 512) ((__half2*)hsh)[i] = __floats2half2_rn(0.f, 0.f);
    __syncthreads();

    const int arow = tid >> 6;    // 0..7
    const int aj   = tid & 63;    // unit

    const __half* xbase = xw + (size_t)(b0 + arow) * Tc * 256;
    __half px[4];
#pragma unroll
    for (int gg = 0; gg < 4; gg++) px[gg] = xbase[gg * 64 + aj];

    float c = 0.f;

    for (int t = 0; t < Tc; t++) {
        // ---- phase 1: MMA ----
        {
            uint32_t bf[4][2];
            const int l = lane & 15;
            uint32_t baddr = s2u(&hsh[(l & 7) * HP + ((l >> 3) & 1) * 8]);
#pragma unroll
            for (int ks = 0; ks < 4; ks++)
                ldm_x2(bf[ks][0], bf[ks][1], baddr + ks * 32);

            float acc[4] = {0.f, 0.f, 0.f, 0.f};
#pragma unroll
            for (int ks = 0; ks < 4; ks++)
                mma16816(acc, afr[ks], bf[ks]);

            const int gr = w * 16 + (lane >> 2);
            const int n0 = (lane & 3) * 2;
            *(float2*)&gsum[gr * 10 + n0]       = make_float2(acc[0], acc[1]);
            *(float2*)&gsum[(gr + 8) * 10 + n0] = make_float2(acc[2], acc[3]);
        }
        __syncthreads();

        // ---- phase 2 ----
        {
            float zi = gsum[(aj)*10 + arow]       + __half2float(px[0]);
            float zf = gsum[(64 + aj)*10 + arow]  + __half2float(px[1]);
            float zg = gsum[(128 + aj)*10 + arow] + __half2float(px[2]);
            float zo = gsum[(192 + aj)*10 + arow] + __half2float(px[3]);

            c = sigfast(zf) * c + sigfast(zi) * tanhfast(zg);
            float h = sigfast(zo) * tanhfast(c);

            hsh[arow * HP + aj] = __float2half_rn(h);
            if (t == Tc - 1) hfin[arow][aj] = h;

            if (t + 1 < Tc) {
                const __half* xr = xbase + (size_t)(t + 1) * 256;
#pragma unroll
                for (int gg = 0; gg < 4; gg++) px[gg] = xr[gg * 64 + aj];
            }
        }
        __syncthreads();
    }

    // FC head: warp w -> batch row w (warps 0..7), lane = fc1 unit
    if (w < 8) {
        float a = __ldg(fc1b + lane);
#pragma unroll
        for (int k = 0; k < 64; k++)
            a = fmaf(hfin[w][k], __ldg(fc1w + lane * 64 + k), a);
        a = fmaxf(a, 0.f);
        float v = a * __ldg(fc2w + lane);
#pragma unroll
        for (int off = 16; off; off >>= 1) v += __shfl_down_sync(0xffffffffu, v, off);
        if (lane == 0) out[b0 + w] = 1.f / (1.f + __expf(-(v + __ldg(fc2b))));
    }
}

// ---------------------------------------------------------------------------
extern "C" void kernel_launch(void* const* d_in, const int* in_sizes, int n_in,
                              void* d_out, int out_size)
{
    (void)in_sizes; (void)n_in; (void)out_size;
    const float* X     = (const float*)d_in[0];
    const float* W1_ih = (const float*)d_in[1];
    const float* W1_hh = (const float*)d_in[2];
    const float* b1_ih = (const float*)d_in[3];
    const float* b1_hh = (const float*)d_in[4];
    const float* W2_ih = (const float*)d_in[5];
    const float* W2_hh = (const float*)d_in[6];
    const float* b2_ih = (const float*)d_in[7];
    const float* b2_hh = (const float*)d_in[8];
    const float* fc1w  = (const float*)d_in[9];
    const float* fc1b  = (const float*)d_in[10];
    const float* fc2w  = (const float*)d_in[11];
    const float* fc2b  = (const float*)d_in[12];
    float* out = (float*)d_out;

    __half *xw1, *hs1, *xw2;
    cudaGetSymbolAddress((void**)&xw1, g_xw1);
    cudaGetSymbolAddress((void**)&hs1, g_hs1);
    cudaGetSymbolAddress((void**)&xw2, g_xw2);

    // 1) xw1 = half(X @ W1_ih^T + b)
    gemm_hmma<G1c, EMBc, false><<<dim3(G1c / 128, Mtot / 128), 256>>>(X, W1_ih, b1_ih, b1_hh, xw1);
    // 2) layer-1 recurrence (tensor-core)
    lstm1_kernel<<<Bc / 8, 512>>>(xw1, W1_hh, hs1);
    // 3) xw2 = half(hs1 @ W2_ih^T + b)
    gemm_hmma<G2c, H1c, true><<<dim3(G2c / 128, Mtot / 128), 256>>>(hs1, W2_ih, b2_ih, b2_hh, xw2);
    // 4) layer-2 recurrence + FC head (tensor-core)
    lstm2_kernel<<<Bc / 8, 512>>>(xw2, W2_hh, fc1w, fc1b, fc2w, fc2b, out);
}

// round 8
// speedup vs baseline: 1.9690x; 1.1703x over previous
#include <cuda_runtime.h>
#include <cuda_fp16.h>
#include <cstdint>

// Problem constants
#define Bc   1024
#define Tc   512
#define EMBc 100
#define H1c  128
#define G1c  512   // 4*H1
#define H2c  64
#define G2c  256   // 4*H2
#define Mtot (Bc*Tc)  // 524288

// Scratch (fp16)
__device__ __half g_xw1[(size_t)Mtot * G1c];
__device__ __half g_hs1[(size_t)Mtot * H1c];

// ---------------------------------------------------------------------------
// helpers
// ---------------------------------------------------------------------------
__device__ __forceinline__ uint32_t s2u(const void* p) {
    return (uint32_t)__cvta_generic_to_shared(p);
}
__device__ __forceinline__ void ldm_x4(uint32_t& a0, uint32_t& a1, uint32_t& a2, uint32_t& a3,
                                       uint32_t addr) {
    asm volatile("ldmatrix.sync.aligned.m8n8.x4.shared.b16 {%0,%1,%2,%3}, [%4];"
                 : "=r"(a0), "=r"(a1), "=r"(a2), "=r"(a3) : "r"(addr));
}
__device__ __forceinline__ void ldm_x2(uint32_t& b0, uint32_t& b1, uint32_t addr) {
    asm volatile("ldmatrix.sync.aligned.m8n8.x2.shared.b16 {%0,%1}, [%2];"
                 : "=r"(b0), "=r"(b1) : "r"(addr));
}
__device__ __forceinline__ void mma16816(float* d, const uint32_t* a, const uint32_t* b) {
    asm volatile("mma.sync.aligned.m16n8k16.row.col.f32.f16.f16.f32 "
                 "{%0,%1,%2,%3}, {%4,%5,%6,%7}, {%8,%9}, {%0,%1,%2,%3};"
                 : "+f"(d[0]), "+f"(d[1]), "+f"(d[2]), "+f"(d[3])
                 : "r"(a[0]), "r"(a[1]), "r"(a[2]), "r"(a[3]), "r"(b[0]), "r"(b[1]));
}
__device__ __forceinline__ float tanhfast(float x) {
    float y;
    asm("tanh.approx.f32 %0, %1;" : "=f"(y) : "f"(x));
    return y;
}
__device__ __forceinline__ float sigfast(float x) {
    return 0.5f * tanhfast(0.5f * x) + 0.5f;
}
__device__ __forceinline__ uint32_t packh2(float x, float y) {
    __half2 h = __floats2half2_rn(x, y);
    return *reinterpret_cast<uint32_t*>(&h);
}
__device__ __forceinline__ void cp16(uint32_t smem_addr, const void* gptr) {
    asm volatile("cp.async.cg.shared.global [%0], [%1], 16;" :: "r"(smem_addr), "l"(gptr));
}
__device__ __forceinline__ void cp_commit() {
    asm volatile("cp.async.commit_group;");
}
__device__ __forceinline__ void cp_wait0() {
    asm volatile("cp.async.wait_group 0;");
}

// ---------------------------------------------------------------------------
// fp16 tensor-core GEMM (known-good): out = half(A @ W^T + ba + bb)
// ---------------------------------------------------------------------------
template <int N, int K, bool AHALF>
__global__ void __launch_bounds__(256) gemm_hmma(const void* __restrict__ A_,
                                                 const float* __restrict__ W,
                                                 const float* __restrict__ ba,
                                                 const float* __restrict__ bb,
                                                 __half* __restrict__ out)
{
    constexpr int BM = 128, BN = 128, BK = 32;
    constexpr int LDS_ = 40;
    constexpr int KT = (K + BK - 1) / BK;

    __shared__ alignas(16) __half As[BM * LDS_];
    __shared__ alignas(16) __half Ws[BN * LDS_];

    const int tid  = threadIdx.x;
    const int bm   = blockIdx.y * BM;
    const int bn   = blockIdx.x * BN;
    const int w    = tid >> 5;
    const int lane = tid & 31;
    const int wm   = (w >> 2) * 64;
    const int wn   = (w & 3) * 32;

    float acc[4][4][4];
#pragma unroll
    for (int mt = 0; mt < 4; mt++)
#pragma unroll
        for (int nt = 0; nt < 4; nt++)
#pragma unroll
            for (int i = 0; i < 4; i++) acc[mt][nt][i] = 0.f;

    for (int kt = 0; kt < KT; kt++) {
        const int kbase = kt * BK;
        if constexpr (AHALF) {
            const __half* A = (const __half*)A_;
#pragma unroll
            for (int i = 0; i < 2; i++) {
                int idx = tid + i * 256;
                int m = idx >> 2, c = idx & 3;
                uint4 v = *(const uint4*)(A + (size_t)(bm + m) * K + kbase + c * 8);
                *(uint4*)&As[m * LDS_ + c * 8] = v;
            }
        } else {
            const float* A = (const float*)A_;
#pragma unroll
            for (int i = 0; i < 8; i++) {
                int idx = tid + i * 256;
                int m = idx >> 4, kc = idx & 15;
                int k = kbase + kc * 2;
                float2 v = make_float2(0.f, 0.f);
                if (k + 1 < K)      v = *(const float2*)(A + (size_t)(bm + m) * K + k);
                else if (k < K)     v.x = A[(size_t)(bm + m) * K + k];
                *(__half2*)&As[m * LDS_ + kc * 2] = __floats2half2_rn(v.x, v.y);
            }
        }
#pragma unroll
        for (int i = 0; i < 8; i++) {
            int idx = tid + i * 256;
            int n = idx >> 4, kc = idx & 15;
            int k = kbase + kc * 2;
            float2 v = make_float2(0.f, 0.f);
            if (k + 1 < K)      v = *(const float2*)(W + (size_t)(bn + n) * K + k);
            else if (k < K)     v.x = W[(size_t)(bn + n) * K + k];
            *(__half2*)&Ws[n * LDS_ + kc * 2] = __floats2half2_rn(v.x, v.y);
        }
        __syncthreads();

#pragma unroll
        for (int kk = 0; kk < BK; kk += 16) {
            uint32_t af[4][4];
#pragma unroll
            for (int mt = 0; mt < 4; mt++) {
                uint32_t addr = s2u(&As[(wm + mt * 16 + (lane & 15)) * LDS_ + kk + (lane >> 4) * 8]);
                ldm_x4(af[mt][0], af[mt][1], af[mt][2], af[mt][3], addr);
            }
            uint32_t bf[4][2];
#pragma unroll
            for (int nt = 0; nt < 4; nt++) {
                int l = lane & 15;
                uint32_t addr = s2u(&Ws[(wn + nt * 8 + (l & 7)) * LDS_ + kk + ((l >> 3) & 1) * 8]);
                ldm_x2(bf[nt][0], bf[nt][1], addr);
            }
#pragma unroll
            for (int mt = 0; mt < 4; mt++)
#pragma unroll
                for (int nt = 0; nt < 4; nt++)
                    mma16816(acc[mt][nt], af[mt], bf[nt]);
        }
        __syncthreads();
    }

#pragma unroll
    for (int mt = 0; mt < 4; mt++) {
#pragma unroll
        for (int nt = 0; nt < 4; nt++) {
            int row = bm + wm + mt * 16 + (lane >> 2);
            int col = bn + wn + nt * 8 + (lane & 3) * 2;
            float b0 = __ldg(ba + col) + __ldg(bb + col);
            float b1 = __ldg(ba + col + 1) + __ldg(bb + col + 1);
            *(__half2*)(out + (size_t)row * N + col) =
                __floats2half2_rn(acc[mt][nt][0] + b0, acc[mt][nt][1] + b1);
            *(__half2*)(out + (size_t)(row + 8) * N + col) =
                __floats2half2_rn(acc[mt][nt][2] + b0, acc[mt][nt][3] + b1);
        }
    }
}

// ---------------------------------------------------------------------------
// LSTM layer 1 (tensor-core recurrence) — unchanged from round 7.
// ---------------------------------------------------------------------------
__global__ void __launch_bounds__(512) lstm1_kernel(const __half* __restrict__ xw,   // [B][T][512]
                                                    const float* __restrict__ Whh,   // [512][128]
                                                    __half* __restrict__ hs1)        // [B][T][128]
{
    constexpr int HP = 136;
    __shared__ float  gsum[512 * 10];
    __shared__ __half hsh[8 * HP];

    const int tid  = threadIdx.x;
    const int w    = tid >> 5;
    const int lane = tid & 31;
    const int b0   = blockIdx.x * 8;

    uint32_t afr[2][8][4];
    {
        const int gr = w * 32 + (lane >> 2);
        const int kc = (lane & 3) * 2;
#pragma unroll
        for (int mt = 0; mt < 2; mt++) {
            const float* r0 = Whh + (size_t)(gr + mt * 16) * 128;
            const float* r8 = r0 + 8 * 128;
#pragma unroll
            for (int ks = 0; ks < 8; ks++) {
                int k = ks * 16 + kc;
                afr[mt][ks][0] = packh2(r0[k],     r0[k + 1]);
                afr[mt][ks][1] = packh2(r8[k],     r8[k + 1]);
                afr[mt][ks][2] = packh2(r0[k + 8], r0[k + 9]);
                afr[mt][ks][3] = packh2(r8[k + 8], r8[k + 9]);
            }
        }
    }

    for (int i = tid; i < 8 * HP / 2; i += 512) ((__half2*)hsh)[i] = __floats2half2_rn(0.f, 0.f);
    __syncthreads();

    const int arow = tid >> 6;
    const int aj2  = (tid & 63) * 2;

    const __half* xbase = xw + (size_t)(b0 + arow) * Tc * 512;
    __half2 px[4];
#pragma unroll
    for (int gg = 0; gg < 4; gg++)
        px[gg] = *(const __half2*)(xbase + gg * 128 + aj2);

    float c0 = 0.f, c1 = 0.f;

    for (int t = 0; t < Tc; t++) {
        {
            uint32_t bf[8][2];
            const int l = lane & 15;
            uint32_t baddr = s2u(&hsh[(l & 7) * HP + ((l >> 3) & 1) * 8]);
#pragma unroll
            for (int ks = 0; ks < 8; ks++)
                ldm_x2(bf[ks][0], bf[ks][1], baddr + ks * 32);

            float acc[2][4];
#pragma unroll
            for (int mt = 0; mt < 2; mt++) {
#pragma unroll
                for (int i = 0; i < 4; i++) acc[mt][i] = 0.f;
#pragma unroll
                for (int ks = 0; ks < 8; ks++)
                    mma16816(acc[mt], afr[mt][ks], bf[ks]);
            }
            const int gr = w * 32 + (lane >> 2);
            const int n0 = (lane & 3) * 2;
#pragma unroll
            for (int mt = 0; mt < 2; mt++) {
                *(float2*)&gsum[(gr + mt * 16) * 10 + n0]     = make_float2(acc[mt][0], acc[mt][1]);
                *(float2*)&gsum[(gr + mt * 16 + 8) * 10 + n0] = make_float2(acc[mt][2], acc[mt][3]);
            }
        }
        __syncthreads();

        {
            float2 p0 = __half22float2(px[0]);
            float2 p1 = __half22float2(px[1]);
            float2 p2 = __half22float2(px[2]);
            float2 p3 = __half22float2(px[3]);
            float zi0 = gsum[(aj2)*10 + arow]           + p0.x;
            float zi1 = gsum[(aj2 + 1)*10 + arow]       + p0.y;
            float zf0 = gsum[(128 + aj2)*10 + arow]     + p1.x;
            float zf1 = gsum[(128 + aj2 + 1)*10 + arow] + p1.y;
            float zg0 = gsum[(256 + aj2)*10 + arow]     + p2.x;
            float zg1 = gsum[(256 + aj2 + 1)*10 + arow] + p2.y;
            float zo0 = gsum[(384 + aj2)*10 + arow]     + p3.x;
            float zo1 = gsum[(384 + aj2 + 1)*10 + arow] + p3.y;

            c0 = sigfast(zf0) * c0 + sigfast(zi0) * tanhfast(zg0);
            float h0 = sigfast(zo0) * tanhfast(c0);
            c1 = sigfast(zf1) * c1 + sigfast(zi1) * tanhfast(zg1);
            float h1 = sigfast(zo1) * tanhfast(c1);

            __half2 hh = __floats2half2_rn(h0, h1);
            *(__half2*)&hsh[arow * HP + aj2] = hh;
            *(__half2*)(hs1 + ((size_t)(b0 + arow) * Tc + t) * 128 + aj2) = hh;

            if (t + 1 < Tc) {
                const __half* xr = xbase + (size_t)(t + 1) * 512;
#pragma unroll
                for (int gg = 0; gg < 4; gg++)
                    px[gg] = *(const __half2*)(xr + gg * 128 + aj2);
            }
        }
        __syncthreads();
    }
}

// ---------------------------------------------------------------------------
// LSTM layer 2 with FUSED input projection + FC head.
// gates2_t = W2_ih @ h1_t + W2_hh @ h2_{t-1} + b2, all in one MMA accumulator.
// h1_t tiles (8x128 fp16) cp.async double-buffer prefetched from hs1 gmem.
// 128 blocks x 512 threads; warp w owns gates [w*16, w*16+16).
// ---------------------------------------------------------------------------
__global__ void __launch_bounds__(512) lstm2_kernel(const __half* __restrict__ hs1,  // [B][T][128]
                                                    const float* __restrict__ Whh,   // [256][64]
                                                    const float* __restrict__ Wih,   // [256][128]
                                                    const float* __restrict__ b_ih,
                                                    const float* __restrict__ b_hh,
                                                    const float* __restrict__ fc1w,
                                                    const float* __restrict__ fc1b,
                                                    const float* __restrict__ fc2w,
                                                    const float* __restrict__ fc2b,
                                                    float* __restrict__ out)
{
    constexpr int HP = 72;                    // padded h2 row (halves)
    constexpr int XP = 136;                   // padded h1 buffer row (halves)
    __shared__ float  gsum[256 * 10];         // 10KB
    __shared__ __half hsh[8 * HP];            // 1.1KB
    __shared__ alignas(16) __half xbuf[2][8 * XP];  // 4.3KB
    __shared__ float  hfin[8][64];            // 2KB

    const int tid  = threadIdx.x;
    const int w    = tid >> 5;
    const int lane = tid & 31;
    const int b0   = blockIdx.x * 8;

    // ---- persistent weight fragments ----
    const int gr = w * 16 + (lane >> 2);
    const int kc = (lane & 3) * 2;
    uint32_t ahh[4][4];
    {
        const float* r0 = Whh + (size_t)gr * 64;
        const float* r8 = r0 + 8 * 64;
#pragma unroll
        for (int ks = 0; ks < 4; ks++) {
            int k = ks * 16 + kc;
            ahh[ks][0] = packh2(r0[k],     r0[k + 1]);
            ahh[ks][1] = packh2(r8[k],     r8[k + 1]);
            ahh[ks][2] = packh2(r0[k + 8], r0[k + 9]);
            ahh[ks][3] = packh2(r8[k + 8], r8[k + 9]);
        }
    }
    uint32_t aih[8][4];
    {
        const float* r0 = Wih + (size_t)gr * 128;
        const float* r8 = r0 + 8 * 128;
#pragma unroll
        for (int ks = 0; ks < 8; ks++) {
            int k = ks * 16 + kc;
            aih[ks][0] = packh2(r0[k],     r0[k + 1]);
            aih[ks][1] = packh2(r8[k],     r8[k + 1]);
            aih[ks][2] = packh2(r0[k + 8], r0[k + 9]);
            aih[ks][3] = packh2(r8[k + 8], r8[k + 9]);
        }
    }
    const float b2lo = __ldg(b_ih + gr)     + __ldg(b_hh + gr);
    const float b2hi = __ldg(b_ih + gr + 8) + __ldg(b_hh + gr + 8);

    // zero h2 state
    for (int i = tid; i < 8 * HP / 2; i += 512) ((__half2*)hsh)[i] = __floats2half2_rn(0.f, 0.f);

    // prologue: prefetch h1 tile for t=0
    const int cr = tid >> 4, cc = tid & 15;   // row 0..7, 16B-chunk 0..15
    if (tid < 128) {
        cp16(s2u(&xbuf[0][cr * XP + cc * 8]),
             hs1 + ((size_t)(b0 + cr) * Tc + 0) * 128 + cc * 8);
        cp_commit();
        cp_wait0();
    }
    __syncthreads();

    const int arow = tid >> 6;    // 0..7
    const int aj   = tid & 63;    // unit

    float c = 0.f;

    for (int t = 0; t < Tc; t++) {
        // prefetch h1 tile for t+1 (latency hidden by the whole step)
        if (tid < 128 && t + 1 < Tc) {
            cp16(s2u(&xbuf[(t + 1) & 1][cr * XP + cc * 8]),
                 hs1 + ((size_t)(b0 + cr) * Tc + (t + 1)) * 128 + cc * 8);
            cp_commit();
        }

        // ---- phase 1: gates = Wih@h1 + Whh@h2prev + b2 ----
        {
            const int l = lane & 15;
            const __half* xb = xbuf[t & 1];
            uint32_t b1addr = s2u(&xb[(l & 7) * XP + ((l >> 3) & 1) * 8]);
            uint32_t bh1[8][2];
#pragma unroll
            for (int ks = 0; ks < 8; ks++)
                ldm_x2(bh1[ks][0], bh1[ks][1], b1addr + ks * 32);

            uint32_t b2addr = s2u(&hsh[(l & 7) * HP + ((l >> 3) & 1) * 8]);
            uint32_t bh2[4][2];
#pragma unroll
            for (int ks = 0; ks < 4; ks++)
                ldm_x2(bh2[ks][0], bh2[ks][1], b2addr + ks * 32);

            float acc[4] = {b2lo, b2lo, b2hi, b2hi};
#pragma unroll
            for (int ks = 0; ks < 4; ks++)
                mma16816(acc, ahh[ks], bh2[ks]);
#pragma unroll
            for (int ks = 0; ks < 8; ks++)
                mma16816(acc, aih[ks], bh1[ks]);

            const int n0 = (lane & 3) * 2;
            *(float2*)&gsum[gr * 10 + n0]       = make_float2(acc[0], acc[1]);
            *(float2*)&gsum[(gr + 8) * 10 + n0] = make_float2(acc[2], acc[3]);
        }
        __syncthreads();

        // ---- phase 2: activations ----
        {
            float zi = gsum[(aj)*10 + arow];
            float zf = gsum[(64 + aj)*10 + arow];
            float zg = gsum[(128 + aj)*10 + arow];
            float zo = gsum[(192 + aj)*10 + arow];

            c = sigfast(zf) * c + sigfast(zi) * tanhfast(zg);
            float h = sigfast(zo) * tanhfast(c);

            hsh[arow * HP + aj] = __float2half_rn(h);
            if (t == Tc - 1) hfin[arow][aj] = h;
        }
        if (tid < 128) cp_wait0();   // h1 tile for t+1 landed (issued a full step ago)
        __syncthreads();
    }

    // FC head: warp w -> batch row w (warps 0..7), lane = fc1 unit
    if (w < 8) {
        float a = __ldg(fc1b + lane);
#pragma unroll
        for (int k = 0; k < 64; k++)
            a = fmaf(hfin[w][k], __ldg(fc1w + lane * 64 + k), a);
        a = fmaxf(a, 0.f);
        float v = a * __ldg(fc2w + lane);
#pragma unroll
        for (int off = 16; off; off >>= 1) v += __shfl_down_sync(0xffffffffu, v, off);
        if (lane == 0) out[b0 + w] = 1.f / (1.f + __expf(-(v + __ldg(fc2b))));
    }
}

// ---------------------------------------------------------------------------
extern "C" void kernel_launch(void* const* d_in, const int* in_sizes, int n_in,
                              void* d_out, int out_size)
{
    (void)in_sizes; (void)n_in; (void)out_size;
    const float* X     = (const float*)d_in[0];
    const float* W1_ih = (const float*)d_in[1];
    const float* W1_hh = (const float*)d_in[2];
    const float* b1_ih = (const float*)d_in[3];
    const float* b1_hh = (const float*)d_in[4];
    const float* W2_ih = (const float*)d_in[5];
    const float* W2_hh = (const float*)d_in[6];
    const float* b2_ih = (const float*)d_in[7];
    const float* b2_hh = (const float*)d_in[8];
    const float* fc1w  = (const float*)d_in[9];
    const float* fc1b  = (const float*)d_in[10];
    const float* fc2w  = (const float*)d_in[11];
    const float* fc2b  = (const float*)d_in[12];
    float* out = (float*)d_out;

    __half *xw1, *hs1;
    cudaGetSymbolAddress((void**)&xw1, g_xw1);
    cudaGetSymbolAddress((void**)&hs1, g_hs1);

    // 1) xw1 = half(X @ W1_ih^T + b)
    gemm_hmma<G1c, EMBc, false><<<dim3(G1c / 128, Mtot / 128), 256>>>(X, W1_ih, b1_ih, b1_hh, xw1);
    // 2) layer-1 recurrence (tensor-core)
    lstm1_kernel<<<Bc / 8, 512>>>(xw1, W1_hh, hs1);
    // 3) layer-2 recurrence with fused input projection + FC head
    lstm2_kernel<<<Bc / 8, 512>>>(hs1, W2_hh, W2_ih, b2_ih, b2_hh,
                                  fc1w, fc1b, fc2w, fc2b, out);
}

// round 9
// speedup vs baseline: 2.3592x; 1.1982x over previous
#include <cuda_runtime.h>
#include <cuda_fp16.h>
#include <cstdint>

// Problem constants
#define Bc   1024
#define Tc   512
#define EMBc 100
#define KP   112   // padded K for layer-1 gemm (fp16, zero-filled)
#define H1c  128
#define G1c  512   // 4*H1
#define H2c  64
#define G2c  256   // 4*H2
#define Mtot (Bc*Tc)  // 524288

// Scratch (fp16)
__device__ __half g_xh [(size_t)Mtot * KP];   // padded fp16 X
__device__ __half g_w1h[(size_t)G1c * KP];    // padded fp16 W1_ih
__device__ __half g_xw1[(size_t)Mtot * G1c];  // layer-1 gate preactivations
__device__ __half g_hs1[(size_t)Mtot * H1c];  // layer-1 hidden states

// ---------------------------------------------------------------------------
// helpers
// ---------------------------------------------------------------------------
__device__ __forceinline__ uint32_t s2u(const void* p) {
    return (uint32_t)__cvta_generic_to_shared(p);
}
__device__ __forceinline__ void ldm_x4(uint32_t& a0, uint32_t& a1, uint32_t& a2, uint32_t& a3,
                                       uint32_t addr) {
    asm volatile("ldmatrix.sync.aligned.m8n8.x4.shared.b16 {%0,%1,%2,%3}, [%4];"
                 : "=r"(a0), "=r"(a1), "=r"(a2), "=r"(a3) : "r"(addr));
}
__device__ __forceinline__ void ldm_x2(uint32_t& b0, uint32_t& b1, uint32_t addr) {
    asm volatile("ldmatrix.sync.aligned.m8n8.x2.shared.b16 {%0,%1}, [%2];"
                 : "=r"(b0), "=r"(b1) : "r"(addr));
}
__device__ __forceinline__ void mma16816(float* d, const uint32_t* a, const uint32_t* b) {
    asm volatile("mma.sync.aligned.m16n8k16.row.col.f32.f16.f16.f32 "
                 "{%0,%1,%2,%3}, {%4,%5,%6,%7}, {%8,%9}, {%0,%1,%2,%3};"
                 : "+f"(d[0]), "+f"(d[1]), "+f"(d[2]), "+f"(d[3])
                 : "r"(a[0]), "r"(a[1]), "r"(a[2]), "r"(a[3]), "r"(b[0]), "r"(b[1]));
}
__device__ __forceinline__ float tanhfast(float x) {
    float y;
    asm("tanh.approx.f32 %0, %1;" : "=f"(y) : "f"(x));
    return y;
}
__device__ __forceinline__ float sigfast(float x) {
    return 0.5f * tanhfast(0.5f * x) + 0.5f;
}
__device__ __forceinline__ uint32_t packh2(float x, float y) {
    __half2 h = __floats2half2_rn(x, y);
    return *reinterpret_cast<uint32_t*>(&h);
}
__device__ __forceinline__ void cp16(uint32_t smem_addr, const void* gptr) {
    asm volatile("cp.async.cg.shared.global [%0], [%1], 16;" :: "r"(smem_addr), "l"(gptr));
}
__device__ __forceinline__ void cp_commit() { asm volatile("cp.async.commit_group;"); }
__device__ __forceinline__ void cp_wait0()  { asm volatile("cp.async.wait_group 0;"); }

// ---------------------------------------------------------------------------
// fp32 [rows][EMBc] -> fp16 [rows][KP], zero-padded. One half2 per thread.
// ---------------------------------------------------------------------------
__global__ void convert_pad(const float* __restrict__ src, __half* __restrict__ dst, int rows)
{
    int gid = blockIdx.x * blockDim.x + threadIdx.x;
    int total = rows * (KP / 2);
    if (gid >= total) return;
    int row = gid / (KP / 2);
    int p   = gid - row * (KP / 2);
    int k   = 2 * p;
    float x0 = (k < EMBc)     ? src[(size_t)row * EMBc + k]     : 0.f;
    float x1 = (k + 1 < EMBc) ? src[(size_t)row * EMBc + k + 1] : 0.f;
    *(__half2*)(dst + (size_t)row * KP + k) = __floats2half2_rn(x0, x1);
}

// ---------------------------------------------------------------------------
// Layer-1 GEMM, all fp16 in / fp16 out, K=112 in one smem tile (no k-loop).
// out[m][n] = half(sum_k A[m][k]*W[n][k] + ba[n] + bb[n])
// BM=128, BN=128, 256 threads, warp grid 2(m) x 4(n), cp.async loads.
// ---------------------------------------------------------------------------
__global__ void __launch_bounds__(256) gemm1h(const __half* __restrict__ A,   // [M][112]
                                              const __half* __restrict__ W,   // [512][112]
                                              const float* __restrict__ ba,
                                              const float* __restrict__ bb,
                                              __half* __restrict__ out)
{
    constexpr int LDSs = 120;   // padded half stride (240B, conflict-free ldmatrix)
    __shared__ alignas(16) __half As[128 * LDSs];
    __shared__ alignas(16) __half Ws[128 * LDSs];

    const int tid  = threadIdx.x;
    const int bm   = blockIdx.y * 128;
    const int bn   = blockIdx.x * 128;
    const int w    = tid >> 5;
    const int lane = tid & 31;
    const int wm   = (w >> 2) * 64;
    const int wn   = (w & 3) * 32;

    // cp.async the whole K: 128 rows x 14 chunks of 16B, for A and W
    {
        const int m = tid >> 1;
#pragma unroll
        for (int c = 0; c < 7; c++) {
            int cc = c * 2 + (tid & 1);
            cp16(s2u(&As[m * LDSs + cc * 8]), A + (size_t)(bm + m) * KP + cc * 8);
            cp16(s2u(&Ws[m * LDSs + cc * 8]), W + (size_t)(bn + m) * KP + cc * 8);
        }
        cp_commit();
        cp_wait0();
    }
    __syncthreads();

    float acc[4][4][4];
#pragma unroll
    for (int mt = 0; mt < 4; mt++)
#pragma unroll
        for (int nt = 0; nt < 4; nt++)
#pragma unroll
            for (int i = 0; i < 4; i++) acc[mt][nt][i] = 0.f;

#pragma unroll
    for (int ks = 0; ks < 7; ks++) {
        uint32_t af[4][4];
#pragma unroll
        for (int mt = 0; mt < 4; mt++) {
            uint32_t addr = s2u(&As[(wm + mt * 16 + (lane & 15)) * LDSs + ks * 16 + (lane >> 4) * 8]);
            ldm_x4(af[mt][0], af[mt][1], af[mt][2], af[mt][3], addr);
        }
        uint32_t bf[4][2];
#pragma unroll
        for (int nt = 0; nt < 4; nt++) {
            int l = lane & 15;
            uint32_t addr = s2u(&Ws[(wn + nt * 8 + (l & 7)) * LDSs + ks * 16 + ((l >> 3) & 1) * 8]);
            ldm_x2(bf[nt][0], bf[nt][1], addr);
        }
#pragma unroll
        for (int mt = 0; mt < 4; mt++)
#pragma unroll
            for (int nt = 0; nt < 4; nt++)
                mma16816(acc[mt][nt], af[mt], bf[nt]);
    }

#pragma unroll
    for (int mt = 0; mt < 4; mt++) {
#pragma unroll
        for (int nt = 0; nt < 4; nt++) {
            int row = bm + wm + mt * 16 + (lane >> 2);
            int col = bn + wn + nt * 8 + (lane & 3) * 2;
            float b0 = __ldg(ba + col) + __ldg(bb + col);
            float b1 = __ldg(ba + col + 1) + __ldg(bb + col + 1);
            *(__half2*)(out + (size_t)row * G1c + col) =
                __floats2half2_rn(acc[mt][nt][0] + b0, acc[mt][nt][1] + b1);
            *(__half2*)(out + (size_t)(row + 8) * G1c + col) =
                __floats2half2_rn(acc[mt][nt][2] + b0, acc[mt][nt][3] + b1);
        }
    }
}

// ---------------------------------------------------------------------------
// LSTM layer 1: gate-permuted tensor-core recurrence, in-register activations.
// 128 blocks x 512 threads, 8 batch rows/block. Warp w: m16 tile mt holds
// rows = gate gt (rr>>2) of units u = w*8 + mt*4 + (rr&3). After MMA,
// lanes r<4 hold (i,g), lanes r>=4 hold (f,o) of the same unit -> shfl.xor 16
// exchange -> full activation in registers. ONE barrier per step.
// xw1 tiles cp.async double-buffered (1-step lookahead), folded into acc init.
// ---------------------------------------------------------------------------
__global__ void __launch_bounds__(512) lstm1_kernel(const __half* __restrict__ xw,   // [B][T][512]
                                                    const float* __restrict__ Whh,   // [512][128]
                                                    __half* __restrict__ hs1)        // [B][T][128]
{
    constexpr int HP = 72;     // padded h row (halves): 64 used of 72? no: H1=128 -> use 136
    constexpr int HP1 = 136;
    constexpr int XP = 520;    // padded xw row (halves)
    __shared__ __half hsh[2][8 * HP1];
    __shared__ alignas(16) __half xwb[2][8 * XP];
    (void)HP;

    const int tid  = threadIdx.x;
    const int w    = tid >> 5;
    const int lane = tid & 31;
    const int b0   = blockIdx.x * 8;
    const int r    = lane >> 2;
    const int q    = lane & 3;
    const int n0   = q * 2;
    const bool lo  = (r < 4);

    // permuted row mapping
    int uu[2], Glo[2], Ghi[2];
#pragma unroll
    for (int mt = 0; mt < 2; mt++) {
        uu[mt]  = w * 8 + mt * 4 + (r & 3);
        Glo[mt] = (r >> 2) * H1c + uu[mt];          // gate 0/1 (i or f)
        Ghi[mt] = ((r + 8) >> 2) * H1c + uu[mt];    // gate 2/3 (g or o)
    }

    // persistent A fragments (permuted W_hh rows, fp16)
    uint32_t afr[2][8][4];
#pragma unroll
    for (int mt = 0; mt < 2; mt++) {
        const float* rl = Whh + (size_t)Glo[mt] * H1c;
        const float* rh = Whh + (size_t)Ghi[mt] * H1c;
#pragma unroll
        for (int ks = 0; ks < 8; ks++) {
            int k = ks * 16 + q * 2;
            afr[mt][ks][0] = packh2(rl[k],     rl[k + 1]);
            afr[mt][ks][1] = packh2(rh[k],     rh[k + 1]);
            afr[mt][ks][2] = packh2(rl[k + 8], rl[k + 9]);
            afr[mt][ks][3] = packh2(rh[k + 8], rh[k + 9]);
        }
    }

    // zero h state (both buffers)
    for (int i = tid; i < 2 * 8 * HP1 / 2; i += 512)
        ((__half2*)hsh)[i] = __floats2half2_rn(0.f, 0.f);

    // prefetch xw tile for t=0
    {
        int row = tid >> 6, ch = tid & 63;
        cp16(s2u(&xwb[0][row * XP + ch * 8]),
             xw + ((size_t)(b0 + row) * Tc + 0) * G1c + ch * 8);
        cp_commit();
        cp_wait0();
    }
    __syncthreads();

    const int ncol = n0 + (lo ? 0 : 1);
    float cst[2] = {0.f, 0.f};

    for (int t = 0; t < Tc; t++) {
        // prefetch xw tile for t+1
        if (t + 1 < Tc) {
            int row = tid >> 6, ch = tid & 63;
            cp16(s2u(&xwb[(t + 1) & 1][row * XP + ch * 8]),
                 xw + ((size_t)(b0 + row) * Tc + (t + 1)) * G1c + ch * 8);
            cp_commit();
        }

        const __half* xb = xwb[t & 1];
        const __half* hb = hsh[t & 1];

        // B fragments: h_{t-1}
        uint32_t bf[8][2];
        {
            const int l = lane & 15;
            uint32_t baddr = s2u(&hb[(l & 7) * HP1 + ((l >> 3) & 1) * 8]);
#pragma unroll
            for (int ks = 0; ks < 8; ks++)
                ldm_x2(bf[ks][0], bf[ks][1], baddr + ks * 32);
        }

#pragma unroll
        for (int mt = 0; mt < 2; mt++) {
            float acc[4];
            acc[0] = __half2float(xb[n0 * XP + Glo[mt]]);
            acc[1] = __half2float(xb[(n0 + 1) * XP + Glo[mt]]);
            acc[2] = __half2float(xb[n0 * XP + Ghi[mt]]);
            acc[3] = __half2float(xb[(n0 + 1) * XP + Ghi[mt]]);
#pragma unroll
            for (int ks = 0; ks < 8; ks++)
                mma16816(acc, afr[mt][ks], bf[ks]);

            // exchange: lo sends (col n1) of its gates, hi sends (col n0)
            float s0 = lo ? acc[1] : acc[0];
            float s1 = lo ? acc[3] : acc[2];
            float r0 = __shfl_xor_sync(0xffffffffu, s0, 16);
            float r1 = __shfl_xor_sync(0xffffffffu, s1, 16);
            float zi = lo ? acc[0] : r0;
            float zf = lo ? r0     : acc[1];
            float zg = lo ? acc[2] : r1;
            float zo = lo ? r1     : acc[3];

            cst[mt] = sigfast(zf) * cst[mt] + sigfast(zi) * tanhfast(zg);
            float h = sigfast(zo) * tanhfast(cst[mt]);

            __half hh = __float2half_rn(h);
            hsh[(t + 1) & 1][ncol * HP1 + uu[mt]] = hh;
            hs1[((size_t)(b0 + ncol) * Tc + t) * H1c + uu[mt]] = hh;
        }
        cp_wait0();
        __syncthreads();
    }
}

// ---------------------------------------------------------------------------
// LSTM layer 2 (gate-permuted, fused input projection) + FC head.
// gates2 = W2_ih @ h1_t + W2_hh @ h2_{t-1} + b2 in one accumulator set.
// 128 blocks x 512 threads; warp w: 1 m16 tile = 4 gates x units w*4..w*4+3.
// ---------------------------------------------------------------------------
__global__ void __launch_bounds__(512) lstm2_kernel(const __half* __restrict__ hs1,  // [B][T][128]
                                                    const float* __restrict__ Whh,   // [256][64]
                                                    const float* __restrict__ Wih,   // [256][128]
                                                    const float* __restrict__ b_ih,
                                                    const float* __restrict__ b_hh,
                                                    const float* __restrict__ fc1w,
                                                    const float* __restrict__ fc1b,
                                                    const float* __restrict__ fc2w,
                                                    const float* __restrict__ fc2b,
                                                    float* __restrict__ out)
{
    constexpr int HP = 72;     // padded h2 row (halves)
    constexpr int XP = 136;    // padded h1 row (halves)
    __shared__ __half hsh[2][8 * HP];
    __shared__ alignas(16) __half xb[2][8 * XP];
    __shared__ float hfin[8][64];

    const int tid  = threadIdx.x;
    const int w    = tid >> 5;
    const int lane = tid & 31;
    const int b0   = blockIdx.x * 8;
    const int r    = lane >> 2;
    const int q    = lane & 3;
    const int n0   = q * 2;
    const bool lo  = (r < 4);

    const int u   = w * 4 + (r & 3);
    const int Glo = (r >> 2) * H2c + u;
    const int Ghi = ((r + 8) >> 2) * H2c + u;

    // persistent fragments
    uint32_t ahh[4][4];
    {
        const float* rl = Whh + (size_t)Glo * H2c;
        const float* rh = Whh + (size_t)Ghi * H2c;
#pragma unroll
        for (int ks = 0; ks < 4; ks++) {
            int k = ks * 16 + q * 2;
            ahh[ks][0] = packh2(rl[k],     rl[k + 1]);
            ahh[ks][1] = packh2(rh[k],     rh[k + 1]);
            ahh[ks][2] = packh2(rl[k + 8], rl[k + 9]);
            ahh[ks][3] = packh2(rh[k + 8], rh[k + 9]);
        }
    }
    uint32_t aih[8][4];
    {
        const float* rl = Wih + (size_t)Glo * H1c;
        const float* rh = Wih + (size_t)Ghi * H1c;
#pragma unroll
        for (int ks = 0; ks < 8; ks++) {
            int k = ks * 16 + q * 2;
            aih[ks][0] = packh2(rl[k],     rl[k + 1]);
            aih[ks][1] = packh2(rh[k],     rh[k + 1]);
            aih[ks][2] = packh2(rl[k + 8], rl[k + 9]);
            aih[ks][3] = packh2(rh[k + 8], rh[k + 9]);
        }
    }
    const float blo = __ldg(b_ih + Glo) + __ldg(b_hh + Glo);
    const float bhi = __ldg(b_ih + Ghi) + __ldg(b_hh + Ghi);

    for (int i = tid; i < 2 * 8 * HP / 2; i += 512)
        ((__half2*)hsh)[i] = __floats2half2_rn(0.f, 0.f);

    // prefetch h1 tile for t=0 (8 rows x 16 chunks)
    if (tid < 128) {
        int row = tid >> 4, ch = tid & 15;
        cp16(s2u(&xb[0][row * XP + ch * 8]),
             hs1 + ((size_t)(b0 + row) * Tc + 0) * H1c + ch * 8);
        cp_commit();
        cp_wait0();
    }
    __syncthreads();

    const int ncol = n0 + (lo ? 0 : 1);
    float cst = 0.f;

    for (int t = 0; t < Tc; t++) {
        if (tid < 128 && t + 1 < Tc) {
            int row = tid >> 4, ch = tid & 15;
            cp16(s2u(&xb[(t + 1) & 1][row * XP + ch * 8]),
                 hs1 + ((size_t)(b0 + row) * Tc + (t + 1)) * H1c + ch * 8);
            cp_commit();
        }

        const __half* x1 = xb[t & 1];
        const __half* hb = hsh[t & 1];
        const int l = lane & 15;

        uint32_t bh1[8][2];
        {
            uint32_t baddr = s2u(&x1[(l & 7) * XP + ((l >> 3) & 1) * 8]);
#pragma unroll
            for (int ks = 0; ks < 8; ks++)
                ldm_x2(bh1[ks][0], bh1[ks][1], baddr + ks * 32);
        }
        uint32_t bh2[4][2];
        {
            uint32_t baddr = s2u(&hb[(l & 7) * HP + ((l >> 3) & 1) * 8]);
#pragma unroll
            for (int ks = 0; ks < 4; ks++)
                ldm_x2(bh2[ks][0], bh2[ks][1], baddr + ks * 32);
        }

        float acc[4] = {blo, blo, bhi, bhi};
#pragma unroll
        for (int ks = 0; ks < 4; ks++)
            mma16816(acc, ahh[ks], bh2[ks]);
#pragma unroll
        for (int ks = 0; ks < 8; ks++)
            mma16816(acc, aih[ks], bh1[ks]);

        float s0 = lo ? acc[1] : acc[0];
        float s1 = lo ? acc[3] : acc[2];
        float r0 = __shfl_xor_sync(0xffffffffu, s0, 16);
        float r1 = __shfl_xor_sync(0xffffffffu, s1, 16);
        float zi = lo ? acc[0] : r0;
        float zf = lo ? r0     : acc[1];
        float zg = lo ? acc[2] : r1;
        float zo = lo ? r1     : acc[3];

        cst = sigfast(zf) * cst + sigfast(zi) * tanhfast(zg);
        float h = sigfast(zo) * tanhfast(cst);

        hsh[(t + 1) & 1][ncol * HP + u] = __float2half_rn(h);
        if (t == Tc - 1) hfin[ncol][u] = h;

        if (tid < 128) cp_wait0();
        __syncthreads();
    }

    // FC head: warp w -> batch row w (warps 0..7), lane = fc1 unit
    if (w < 8) {
        float a = __ldg(fc1b + lane);
#pragma unroll
        for (int k = 0; k < 64; k++)
            a = fmaf(hfin[w][k], __ldg(fc1w + lane * 64 + k), a);
        a = fmaxf(a, 0.f);
        float v = a * __ldg(fc2w + lane);
#pragma unroll
        for (int off = 16; off; off >>= 1) v += __shfl_down_sync(0xffffffffu, v, off);
        if (lane == 0) out[b0 + w] = 1.f / (1.f + __expf(-(v + __ldg(fc2b))));
    }
}

// ---------------------------------------------------------------------------
extern "C" void kernel_launch(void* const* d_in, const int* in_sizes, int n_in,
                              void* d_out, int out_size)
{
    (void)in_sizes; (void)n_in; (void)out_size;
    const float* X     = (const float*)d_in[0];
    const float* W1_ih = (const float*)d_in[1];
    const float* W1_hh = (const float*)d_in[2];
    const float* b1_ih = (const float*)d_in[3];
    const float* b1_hh = (const float*)d_in[4];
    const float* W2_ih = (const float*)d_in[5];
    const float* W2_hh = (const float*)d_in[6];
    const float* b2_ih = (const float*)d_in[7];
    const float* b2_hh = (const float*)d_in[8];
    const float* fc1w  = (const float*)d_in[9];
    const float* fc1b  = (const float*)d_in[10];
    const float* fc2w  = (const float*)d_in[11];
    const float* fc2b  = (const float*)d_in[12];
    float* out = (float*)d_out;

    __half *xh, *w1h, *xw1, *hs1;
    cudaGetSymbolAddress((void**)&xh,  g_xh);
    cudaGetSymbolAddress((void**)&w1h, g_w1h);
    cudaGetSymbolAddress((void**)&xw1, g_xw1);
    cudaGetSymbolAddress((void**)&hs1, g_hs1);

    // 0) pad+convert X and W1_ih to fp16 [.. ][112]
    convert_pad<<<(Mtot * (KP / 2) + 255) / 256, 256>>>(X, xh, Mtot);
    convert_pad<<<(G1c * (KP / 2) + 255) / 256, 256>>>(W1_ih, w1h, G1c);
    // 1) xw1 = half(X @ W1_ih^T + b)   (all-fp16 single-K-tile GEMM)
    gemm1h<<<dim3(G1c / 128, Mtot / 128), 256>>>(xh, w1h, b1_ih, b1_hh, xw1);
    // 2) layer-1 recurrence (gate-permuted tensor-core)
    lstm1_kernel<<<Bc / 8, 512>>>(xw1, W1_hh, hs1);
    // 3) layer-2 recurrence (fused input projection) + FC head
    lstm2_kernel<<<Bc / 8, 512>>>(hs1, W2_hh, W2_ih, b2_ih, b2_hh,
                                  fc1w, fc1b, fc2w, fc2b, out);
}